// round 6
// baseline (speedup 1.0000x reference)
#include <cuda_runtime.h>
#include <cuda_pipeline_primitives.h>

// out[b,e,t] = v2[t]*x[b,e,t] + bias[t] + P[t]
// P[t] = sum_{s<t} x[b,e,s]*w[s]*d^(t-s),  d = clip(decay[1], 0.9, 1.0)
//
// Decayed prefix scan along S. All scan multipliers are data-independent
// powers of d -> only the additive term is shuffled. x rows are staged
// through shared memory with cp.async (depth-4 pipeline): load latency is
// hidden 3 rows ahead at zero register cost. Each thread stages and consumes
// only its own 32B, so no extra barriers are required.

#define SEQ 2048
#define CHUNK 8
#define THREADS 256          // 256 * 8 = 2048 = SEQ
#define NWARP (THREADS / 32)
#define RPB 8                // rows per block
#define STAGES 4

__global__ void __launch_bounds__(THREADS)
decay_scan_kernel(const float* __restrict__ x,
                  const float* __restrict__ w,
                  const float* __restrict__ v2,
                  const float* __restrict__ bias,
                  const float* __restrict__ decay,
                  float* __restrict__ out,
                  int rows)
{
    const int tid   = threadIdx.x;
    const int lane  = tid & 31;
    const int warp  = tid >> 5;
    const int sbase = tid * CHUNK;

    const float d = fminf(fmaxf(decay[1], 0.9f), 1.0f);

    // decay powers (uniform, data-independent)
    float d8 = d * d; d8 = d8 * d8; d8 = d8 * d8;   // d^8
    const float m1  = d8;
    const float m2  = m1 * m1;
    const float m4  = m2 * m2;
    const float m8  = m4 * m4;
    const float m16 = m8 * m8;
    const float d256 = m16 * m16;
    const float Me = exp2f(8.0f * (float)lane * __log2f(d));  // d^(8*lane)

    // register-cached params for this thread's chunk
    float4 w0  = *reinterpret_cast<const float4*>(w    + sbase);
    float4 w1  = *reinterpret_cast<const float4*>(w    + sbase + 4);
    float4 v20 = *reinterpret_cast<const float4*>(v2   + sbase);
    float4 v21 = *reinterpret_cast<const float4*>(v2   + sbase + 4);
    float4 b0  = *reinterpret_cast<const float4*>(bias + sbase);
    float4 b1  = *reinterpret_cast<const float4*>(bias + sbase + 4);
    float wv[CHUNK] = {w0.x, w0.y, w0.z, w0.w, w1.x, w1.y, w1.z, w1.w};
    float vv[CHUNK] = {v20.x, v20.y, v20.z, v20.w, v21.x, v21.y, v21.z, v21.w};
    float bv[CHUNK] = {b0.x, b0.y, b0.z, b0.w, b1.x, b1.y, b1.z, b1.w};

    // x staging buffers: [stage][half][thread] — conflict-free float4 lanes
    __shared__ float4 xs[STAGES][2][THREADS];
    __shared__ float  sA[2][NWARP];

    const int row0 = blockIdx.x * RPB;
    const float* xt = x + (long long)row0 * SEQ + sbase;   // this thread's column

    // prologue: issue stages 0..STAGES-2 (3 rows ahead)
#pragma unroll
    for (int s = 0; s < STAGES - 1; s++) {
        if (s < RPB && row0 + s < rows) {
            __pipeline_memcpy_async(&xs[s][0][tid], xt + (long long)s * SEQ,     16);
            __pipeline_memcpy_async(&xs[s][1][tid], xt + (long long)s * SEQ + 4, 16);
        }
        __pipeline_commit();
    }

#pragma unroll 1
    for (int r = 0; r < RPB; r++) {
        const int row = row0 + r;
        if (row >= rows) break;

        // issue stage r+STAGES-1, keep group count uniform
        {
            const int rn = r + STAGES - 1;
            if (rn < RPB && row0 + rn < rows) {
                __pipeline_memcpy_async(&xs[rn & (STAGES - 1)][0][tid],
                                        xt + (long long)rn * SEQ, 16);
                __pipeline_memcpy_async(&xs[rn & (STAGES - 1)][1][tid],
                                        xt + (long long)rn * SEQ + 4, 16);
            }
            __pipeline_commit();
        }

        // wait for stage r (3 newer groups may stay in flight)
        __pipeline_wait_prior(STAGES - 1);

        const float4 xa0 = xs[r & (STAGES - 1)][0][tid];
        const float4 xa1 = xs[r & (STAGES - 1)][1][tid];
        float xv[CHUNK] = {xa0.x, xa0.y, xa0.z, xa0.w, xa1.x, xa1.y, xa1.z, xa1.w};

        // per-chunk additive term: A = sum_j x[j]*w[j]*d^(CHUNK-j)
        float A = 0.f;
#pragma unroll
        for (int j = 0; j < CHUNK; j++) A = d * fmaf(xv[j], wv[j], A);

        // Kogge-Stone scan of A (multipliers precomputed)
        float Ai = A;
        {
            float ap;
            ap = __shfl_up_sync(0xffffffffu, Ai, 1);  if (lane >= 1)  Ai = fmaf(m1,  ap, Ai);
            ap = __shfl_up_sync(0xffffffffu, Ai, 2);  if (lane >= 2)  Ai = fmaf(m2,  ap, Ai);
            ap = __shfl_up_sync(0xffffffffu, Ai, 4);  if (lane >= 4)  Ai = fmaf(m4,  ap, Ai);
            ap = __shfl_up_sync(0xffffffffu, Ai, 8);  if (lane >= 8)  Ai = fmaf(m8,  ap, Ai);
            ap = __shfl_up_sync(0xffffffffu, Ai, 16); if (lane >= 16) Ai = fmaf(m16, ap, Ai);
        }

        const int p = r & 1;
        if (lane == 31) sA[p][warp] = Ai;
        __syncthreads();

        // cross-warp carry (uniform multiplier d^256)
        float Cw = 0.f;
#pragma unroll
        for (int wi = 0; wi < NWARP; wi++)
            if (wi < warp) Cw = fmaf(d256, Cw, sA[p][wi]);

        // exclusive additive within warp
        float Ae = __shfl_up_sync(0xffffffffu, Ai, 1);
        if (lane == 0) Ae = 0.f;

        float C = fmaf(Me, Cw, Ae);   // P at start of this thread's chunk

        // epilogue: out[t] = v2[t]*x[t] + bias[t] + P[t]
        float ov[CHUNK];
#pragma unroll
        for (int j = 0; j < CHUNK; j++) {
            ov[j] = fmaf(vv[j], xv[j], C + bv[j]);
            C = d * fmaf(xv[j], wv[j], C);
        }

        float* op = out + (long long)row * SEQ + sbase;
        *reinterpret_cast<float4*>(op)     = make_float4(ov[0], ov[1], ov[2], ov[3]);
        *reinterpret_cast<float4*>(op + 4) = make_float4(ov[4], ov[5], ov[6], ov[7]);
    }
}

extern "C" void kernel_launch(void* const* d_in, const int* in_sizes, int n_in,
                              void* d_out, int out_size)
{
    const float* x     = (const float*)d_in[0];  // (B, E, S)
    const float* w     = (const float*)d_in[1];  // (1, S)
    const float* v2    = (const float*)d_in[2];  // (1, S)
    const float* bias  = (const float*)d_in[3];  // (S,)
    const float* decay = (const float*)d_in[4];  // (2, 1)
    float* out = (float*)d_out;

    const int rows   = in_sizes[0] / SEQ;        // B * E
    const int blocks = (rows + RPB - 1) / RPB;
    decay_scan_kernel<<<blocks, THREADS>>>(x, w, v2, bias, decay, out, rows);
}

// round 11
// speedup vs baseline: 1.1905x; 1.1905x over previous
#include <cuda_runtime.h>

// out[b,e,t] = v2[t]*x[b,e,t] + bias[t] + P[t]
// P[t] = sum_{s<t} x[b,e,s]*w[s]*d^(t-s),  d = clip(decay[1], 0.9, 1.0)
//
// Decayed prefix scan along S. All scan multipliers are data-independent
// powers of d -> only the additive term is shuffled. No software prefetch:
// register pressure is kept low (launch_bounds minblocks=5) so TLP hides the
// x-load latency. x / out use streaming cache hints (touched exactly once).

#define SEQ 2048
#define CHUNK 8
#define THREADS 256          // 256 * 8 = 2048 = SEQ
#define NWARP (THREADS / 32)
#define RPB 8                // rows per block (params register-cached)

__global__ void __launch_bounds__(THREADS, 5)
decay_scan_kernel(const float* __restrict__ x,
                  const float* __restrict__ w,
                  const float* __restrict__ v2,
                  const float* __restrict__ bias,
                  const float* __restrict__ decay,
                  float* __restrict__ out,
                  int rows)
{
    const int tid   = threadIdx.x;
    const int lane  = tid & 31;
    const int warp  = tid >> 5;
    const int sbase = tid * CHUNK;

    const float d = fminf(fmaxf(decay[1], 0.9f), 1.0f);

    // decay powers (uniform, data-independent)
    float d8 = d * d; d8 = d8 * d8; d8 = d8 * d8;   // d^8
    const float m1  = d8;
    const float m2  = m1 * m1;
    const float m4  = m2 * m2;
    const float m8  = m4 * m4;
    const float m16 = m8 * m8;
    const float d256 = m16 * m16;
    const float Me = exp2f(8.0f * (float)lane * __log2f(d));  // d^(8*lane)

    // register-cached params for this thread's chunk
    float4 w0  = *reinterpret_cast<const float4*>(w    + sbase);
    float4 w1  = *reinterpret_cast<const float4*>(w    + sbase + 4);
    float4 v20 = *reinterpret_cast<const float4*>(v2   + sbase);
    float4 v21 = *reinterpret_cast<const float4*>(v2   + sbase + 4);
    float4 b0  = *reinterpret_cast<const float4*>(bias + sbase);
    float4 b1  = *reinterpret_cast<const float4*>(bias + sbase + 4);
    float wv[CHUNK] = {w0.x, w0.y, w0.z, w0.w, w1.x, w1.y, w1.z, w1.w};
    float vv[CHUNK] = {v20.x, v20.y, v20.z, v20.w, v21.x, v21.y, v21.z, v21.w};
    float bv[CHUNK] = {b0.x, b0.y, b0.z, b0.w, b1.x, b1.y, b1.z, b1.w};

    __shared__ float sA[2][NWARP];

    const int row0 = blockIdx.x * RPB;
    const float* xt = x + (long long)row0 * SEQ + sbase;
    float*       ot = out + (long long)row0 * SEQ + sbase;

#pragma unroll 1
    for (int r = 0; r < RPB; r++) {
        if (row0 + r >= rows) break;   // uniform per block

        // streaming load of this thread's 8 x values (evict-first)
        const float4 xa0 = __ldcs(reinterpret_cast<const float4*>(xt + (long long)r * SEQ));
        const float4 xa1 = __ldcs(reinterpret_cast<const float4*>(xt + (long long)r * SEQ + 4));
        float xv[CHUNK] = {xa0.x, xa0.y, xa0.z, xa0.w, xa1.x, xa1.y, xa1.z, xa1.w};

        // per-chunk additive term: A = sum_j x[j]*w[j]*d^(CHUNK-j)
        float A = 0.f;
#pragma unroll
        for (int j = 0; j < CHUNK; j++) A = d * fmaf(xv[j], wv[j], A);

        // Kogge-Stone scan of A (multipliers precomputed powers of d)
        float Ai = A;
        {
            float ap;
            ap = __shfl_up_sync(0xffffffffu, Ai, 1);  if (lane >= 1)  Ai = fmaf(m1,  ap, Ai);
            ap = __shfl_up_sync(0xffffffffu, Ai, 2);  if (lane >= 2)  Ai = fmaf(m2,  ap, Ai);
            ap = __shfl_up_sync(0xffffffffu, Ai, 4);  if (lane >= 4)  Ai = fmaf(m4,  ap, Ai);
            ap = __shfl_up_sync(0xffffffffu, Ai, 8);  if (lane >= 8)  Ai = fmaf(m8,  ap, Ai);
            ap = __shfl_up_sync(0xffffffffu, Ai, 16); if (lane >= 16) Ai = fmaf(m16, ap, Ai);
        }

        const int p = r & 1;
        if (lane == 31) sA[p][warp] = Ai;
        __syncthreads();

        // cross-warp carry (uniform multiplier d^256)
        float Cw = 0.f;
#pragma unroll
        for (int wi = 0; wi < NWARP; wi++)
            if (wi < warp) Cw = fmaf(d256, Cw, sA[p][wi]);

        // exclusive additive within warp
        float Ae = __shfl_up_sync(0xffffffffu, Ai, 1);
        if (lane == 0) Ae = 0.f;

        float C = fmaf(Me, Cw, Ae);   // P at start of this thread's chunk

        // epilogue: out[t] = v2[t]*x[t] + bias[t] + P[t]
        float ov[CHUNK];
#pragma unroll
        for (int j = 0; j < CHUNK; j++) {
            ov[j] = fmaf(vv[j], xv[j], C + bv[j]);
            C = d * fmaf(xv[j], wv[j], C);
        }

        __stcs(reinterpret_cast<float4*>(ot + (long long)r * SEQ),
               make_float4(ov[0], ov[1], ov[2], ov[3]));
        __stcs(reinterpret_cast<float4*>(ot + (long long)r * SEQ + 4),
               make_float4(ov[4], ov[5], ov[6], ov[7]));
    }
}

extern "C" void kernel_launch(void* const* d_in, const int* in_sizes, int n_in,
                              void* d_out, int out_size)
{
    const float* x     = (const float*)d_in[0];  // (B, E, S)
    const float* w     = (const float*)d_in[1];  // (1, S)
    const float* v2    = (const float*)d_in[2];  // (1, S)
    const float* bias  = (const float*)d_in[3];  // (S,)
    const float* decay = (const float*)d_in[4];  // (2, 1)
    float* out = (float*)d_out;

    const int rows   = in_sizes[0] / SEQ;        // B * E
    const int blocks = (rows + RPB - 1) / RPB;
    decay_scan_kernel<<<blocks, THREADS>>>(x, w, v2, bias, decay, out, rows);
}

// round 12
// speedup vs baseline: 1.2430x; 1.0441x over previous
#include <cuda_runtime.h>

// out[b,e,t] = v2[t]*x[b,e,t] + bias[t] + P[t]
// P[t] = sum_{s<t} x[b,e,s]*w[s]*d^(t-s),  d = clip(decay[1], 0.9, 1.0)
//
// Decayed prefix scan along S. All scan multipliers are data-independent
// powers of d. The A-chain's intermediate values ARE the chunk-local decayed
// prefixes, so the epilogue is fully parallel once the carry C arrives:
//   out[j] = v2[j]*x[j] + (d^j * C + pj[j] + bias[j])
// x prefetched one row ahead in registers; v2/bias staged in padded smem.

#define SEQ 2048
#define CHUNK 8
#define THREADS 256          // 256 * 8 = 2048 = SEQ
#define NWARP (THREADS / 32)
#define RPB 8                // rows per block

__global__ void __launch_bounds__(THREADS, 4)
decay_scan_kernel(const float* __restrict__ x,
                  const float* __restrict__ w,
                  const float* __restrict__ v2,
                  const float* __restrict__ bias,
                  const float* __restrict__ decay,
                  float* __restrict__ out,
                  int rows)
{
    const int tid   = threadIdx.x;
    const int lane  = tid & 31;
    const int warp  = tid >> 5;
    const int sbase = tid * CHUNK;

    const float d = fminf(fmaxf(decay[1], 0.9f), 1.0f);

    // decay powers (uniform, data-independent)
    float d8 = d * d; d8 = d8 * d8; d8 = d8 * d8;   // d^8
    const float m1  = d8;
    const float m2  = m1 * m1;
    const float m4  = m2 * m2;
    const float m8  = m4 * m4;
    const float m16 = m8 * m8;
    const float d256 = m16 * m16;
    const float Me = exp2f(8.0f * (float)lane * __log2f(d));  // d^(8*lane)

    // d^j for j=0..7 (uniform across threads -> uniform registers)
    float dj[CHUNK];
    dj[0] = 1.f;
#pragma unroll
    for (int j = 1; j < CHUNK; j++) dj[j] = dj[j - 1] * d;

    // w register-cached (used in the hot chain)
    const float4 w0 = *reinterpret_cast<const float4*>(w + sbase);
    const float4 w1 = *reinterpret_cast<const float4*>(w + sbase + 4);
    float wv[CHUNK] = {w0.x, w0.y, w0.z, w0.w, w1.x, w1.y, w1.z, w1.w};

    // v2/bias staged in smem (own slot; pad to 5 float4 = 80B for conflict-free LDS.128)
    __shared__ float4 svb[THREADS][5];
    svb[tid][0] = *reinterpret_cast<const float4*>(v2 + sbase);
    svb[tid][1] = *reinterpret_cast<const float4*>(v2 + sbase + 4);
    svb[tid][2] = *reinterpret_cast<const float4*>(bias + sbase);
    svb[tid][3] = *reinterpret_cast<const float4*>(bias + sbase + 4);

    __shared__ float sA[2][NWARP];

    const int row0 = blockIdx.x * RPB;
    const float* xt = x + (long long)row0 * SEQ + sbase;
    float*       ot = out + (long long)row0 * SEQ + sbase;

    // prefetch row 0
    float4 pf0 = make_float4(0.f, 0.f, 0.f, 0.f), pf1 = pf0;
    if (row0 < rows) {
        pf0 = __ldcs(reinterpret_cast<const float4*>(xt));
        pf1 = __ldcs(reinterpret_cast<const float4*>(xt + 4));
    }

#pragma unroll 1
    for (int r = 0; r < RPB; r++) {
        if (row0 + r >= rows) break;   // uniform per block

        const float4 xa0 = pf0, xa1 = pf1;

        // prefetch next row (issued before the scan chain)
        if (r + 1 < RPB && row0 + r + 1 < rows) {
            pf0 = __ldcs(reinterpret_cast<const float4*>(xt + (long long)(r + 1) * SEQ));
            pf1 = __ldcs(reinterpret_cast<const float4*>(xt + (long long)(r + 1) * SEQ + 4));
        }

        float xv[CHUNK] = {xa0.x, xa0.y, xa0.z, xa0.w, xa1.x, xa1.y, xa1.z, xa1.w};

        // A-chain; intermediates are the chunk-local decayed prefixes pj[j]
        float pj[CHUNK];
        float A = 0.f;
#pragma unroll
        for (int j = 0; j < CHUNK; j++) {
            pj[j] = A;
            A = d * fmaf(xv[j], wv[j], A);
        }

        // Kogge-Stone scan of A (multipliers precomputed powers of d)
        float Ai = A;
        {
            float ap;
            ap = __shfl_up_sync(0xffffffffu, Ai, 1);  if (lane >= 1)  Ai = fmaf(m1,  ap, Ai);
            ap = __shfl_up_sync(0xffffffffu, Ai, 2);  if (lane >= 2)  Ai = fmaf(m2,  ap, Ai);
            ap = __shfl_up_sync(0xffffffffu, Ai, 4);  if (lane >= 4)  Ai = fmaf(m4,  ap, Ai);
            ap = __shfl_up_sync(0xffffffffu, Ai, 8);  if (lane >= 8)  Ai = fmaf(m8,  ap, Ai);
            ap = __shfl_up_sync(0xffffffffu, Ai, 16); if (lane >= 16) Ai = fmaf(m16, ap, Ai);
        }

        const int p = r & 1;
        if (lane == 31) sA[p][warp] = Ai;
        __syncthreads();

        // cross-warp carry (uniform multiplier d^256)
        float Cw = 0.f;
#pragma unroll
        for (int wi = 0; wi < NWARP; wi++)
            if (wi < warp) Cw = fmaf(d256, Cw, sA[p][wi]);

        // exclusive additive within warp
        float Ae = __shfl_up_sync(0xffffffffu, Ai, 1);
        if (lane == 0) Ae = 0.f;

        const float C = fmaf(Me, Cw, Ae);   // carry entering this chunk

        // fully parallel epilogue
        const float4 va = svb[tid][0], vb = svb[tid][1];
        const float4 ba = svb[tid][2], bb = svb[tid][3];
        const float vv[CHUNK] = {va.x, va.y, va.z, va.w, vb.x, vb.y, vb.z, vb.w};
        const float bv[CHUNK] = {ba.x, ba.y, ba.z, ba.w, bb.x, bb.y, bb.z, bb.w};

        float ov[CHUNK];
#pragma unroll
        for (int j = 0; j < CHUNK; j++)
            ov[j] = fmaf(vv[j], xv[j], fmaf(dj[j], C, pj[j] + bv[j]));

        __stcs(reinterpret_cast<float4*>(ot + (long long)r * SEQ),
               make_float4(ov[0], ov[1], ov[2], ov[3]));
        __stcs(reinterpret_cast<float4*>(ot + (long long)r * SEQ + 4),
               make_float4(ov[4], ov[5], ov[6], ov[7]));
    }
}

extern "C" void kernel_launch(void* const* d_in, const int* in_sizes, int n_in,
                              void* d_out, int out_size)
{
    const float* x     = (const float*)d_in[0];  // (B, E, S)
    const float* w     = (const float*)d_in[1];  // (1, S)
    const float* v2    = (const float*)d_in[2];  // (1, S)
    const float* bias  = (const float*)d_in[3];  // (S,)
    const float* decay = (const float*)d_in[4];  // (2, 1)
    float* out = (float*)d_out;

    const int rows   = in_sizes[0] / SEQ;        // B * E
    const int blocks = (rows + RPB - 1) / RPB;
    decay_scan_kernel<<<blocks, THREADS>>>(x, w, v2, bias, decay, out, rows);
}